// round 1
// baseline (speedup 1.0000x reference)
#include <cuda_runtime.h>

// Problem constants (fixed by the reference setup)
#define BATCH   4
#define HDIM    256
#define WDIM    256
#define CDIM    192
#define NHEAD   6
#define HEADD   32
#define M_TOK   (BATCH * HDIM * WDIM)   // 262144 tokens
#define NQKV    (3 * CDIM)              // 576
#define NWIN    (BATCH * (HDIM / 8) * (WDIM / 8))  // 4096 windows

// Scratch (no cudaMalloc allowed)
__device__ float g_qkv[(size_t)M_TOK * NQKV];   // 604 MB
__device__ float g_att[(size_t)M_TOK * CDIM];   // 201 MB

// ---------------------------------------------------------------------------
// Tiled SGEMM: C[M,N] = A[M,K] @ W[N,K]^T + bias[N]
// BM=128, BN=64, BK=16, 256 threads, 8x4 micro-tile per thread.
// ---------------------------------------------------------------------------
#define BM 128
#define BN 64
#define BK 16

__global__ __launch_bounds__(256) void sgemm_bias(
    const float* __restrict__ A, const float* __restrict__ W,
    const float* __restrict__ bias, float* __restrict__ C,
    int M, int N, int K)
{
    __shared__ float As[BK][BM];   // transposed: As[k][m]
    __shared__ float Bs[BK][BN];   // transposed: Bs[k][n]

    const int tid = threadIdx.x;
    const int bm = blockIdx.y * BM;
    const int bn = blockIdx.x * BN;
    const int tx = tid & 15;       // 16 col-groups
    const int ty = tid >> 4;       // 16 row-groups

    float acc[8][4];
    #pragma unroll
    for (int i = 0; i < 8; i++)
        #pragma unroll
        for (int j = 0; j < 4; j++) acc[i][j] = 0.f;

    for (int k0 = 0; k0 < K; k0 += BK) {
        // Load A tile (128x16) as 512 float4s; 2 per thread
        #pragma unroll
        for (int q = 0; q < 2; q++) {
            int idx = tid * 2 + q;          // 0..511
            int row = idx >> 2;             // 0..127
            int kc4 = idx & 3;              // which float4 along k
            float4 f = *(const float4*)(A + (size_t)(bm + row) * K + k0 + kc4 * 4);
            As[kc4 * 4 + 0][row] = f.x;
            As[kc4 * 4 + 1][row] = f.y;
            As[kc4 * 4 + 2][row] = f.z;
            As[kc4 * 4 + 3][row] = f.w;
        }
        // Load B tile (64x16) as 256 float4s; 1 per thread
        {
            int row = tid >> 2;             // 0..63
            int kc4 = tid & 3;
            float4 f = *(const float4*)(W + (size_t)(bn + row) * K + k0 + kc4 * 4);
            Bs[kc4 * 4 + 0][row] = f.x;
            Bs[kc4 * 4 + 1][row] = f.y;
            Bs[kc4 * 4 + 2][row] = f.z;
            Bs[kc4 * 4 + 3][row] = f.w;
        }
        __syncthreads();

        #pragma unroll
        for (int k = 0; k < BK; k++) {
            float a[8], b[4];
            #pragma unroll
            for (int i = 0; i < 8; i++) a[i] = As[k][ty * 8 + i];
            #pragma unroll
            for (int j = 0; j < 4; j++) b[j] = Bs[k][tx * 4 + j];
            #pragma unroll
            for (int i = 0; i < 8; i++)
                #pragma unroll
                for (int j = 0; j < 4; j++) acc[i][j] += a[i] * b[j];
        }
        __syncthreads();
    }

    #pragma unroll
    for (int i = 0; i < 8; i++) {
        size_t m = bm + ty * 8 + i;
        #pragma unroll
        for (int j = 0; j < 4; j++) {
            int n = bn + tx * 4 + j;
            C[m * N + n] = acc[i][j] + bias[n];
        }
    }
}

// ---------------------------------------------------------------------------
// Window attention: one block per (window, head). 256 threads.
// q,k,v tiles 64x32 in smem; S 64x64 in smem; softmax; O = S@V.
// Gather/scatter uses the window<->token index map directly (no reorder pass).
// ---------------------------------------------------------------------------
__global__ __launch_bounds__(256) void win_attn(
    const float* __restrict__ bias,
    const float* __restrict__ qkv,
    float* __restrict__ att)
{
    __shared__ float q[64][33];
    __shared__ float k[64][33];
    __shared__ float v[64][33];
    __shared__ float s[64][65];

    const int win = blockIdx.x;
    const int h   = blockIdx.y;
    const int tid = threadIdx.x;

    const int b  = win >> 10;
    const int r  = win & 1023;
    const int wh = r >> 5;
    const int ww = r & 31;

    const float scale = 0.17677669529663687f;  // 1/sqrt(32)

    // Load q (pre-scaled), k, v
    for (int idx = tid; idx < 64 * 32; idx += 256) {
        int i = idx >> 5, d = idx & 31;
        int gh = wh * 8 + (i >> 3);
        int gw = ww * 8 + (i & 7);
        size_t grow = (size_t)b * (HDIM * WDIM) + (size_t)gh * WDIM + gw;
        const float* base = qkv + grow * NQKV + h * HEADD + d;
        q[i][d] = base[0] * scale;
        k[i][d] = base[CDIM];
        v[i][d] = base[2 * CDIM];
    }
    __syncthreads();

    // S = q @ k^T + bias ; thread (ty,tx) computes 4x4 tile
    {
        const int tx = tid & 15, ty = tid >> 4;
        float acc[4][4];
        #pragma unroll
        for (int ii = 0; ii < 4; ii++)
            #pragma unroll
            for (int jj = 0; jj < 4; jj++) acc[ii][jj] = 0.f;

        #pragma unroll
        for (int d = 0; d < 32; d++) {
            float a[4], bb[4];
            #pragma unroll
            for (int ii = 0; ii < 4; ii++) a[ii] = q[ty * 4 + ii][d];
            #pragma unroll
            for (int jj = 0; jj < 4; jj++) bb[jj] = k[tx * 4 + jj][d];
            #pragma unroll
            for (int ii = 0; ii < 4; ii++)
                #pragma unroll
                for (int jj = 0; jj < 4; jj++) acc[ii][jj] += a[ii] * bb[jj];
        }
        #pragma unroll
        for (int ii = 0; ii < 4; ii++) {
            int i = ty * 4 + ii;
            #pragma unroll
            for (int jj = 0; jj < 4; jj++) {
                int j = tx * 4 + jj;
                s[i][j] = acc[ii][jj] + bias[((size_t)h * 64 + i) * 64 + j];
            }
        }
    }
    __syncthreads();

    // Softmax per row: 4 threads per row, 16 cols each
    {
        const int row = tid >> 2, sub = tid & 3;
        float vals[16];
        float mx = -1e30f;
        #pragma unroll
        for (int t = 0; t < 16; t++) {
            vals[t] = s[row][sub * 16 + t];
            mx = fmaxf(mx, vals[t]);
        }
        mx = fmaxf(mx, __shfl_xor_sync(0xffffffffu, mx, 1));
        mx = fmaxf(mx, __shfl_xor_sync(0xffffffffu, mx, 2));
        float sum = 0.f;
        #pragma unroll
        for (int t = 0; t < 16; t++) {
            vals[t] = __expf(vals[t] - mx);
            sum += vals[t];
        }
        sum += __shfl_xor_sync(0xffffffffu, sum, 1);
        sum += __shfl_xor_sync(0xffffffffu, sum, 2);
        float inv = __frcp_rn(sum);
        #pragma unroll
        for (int t = 0; t < 16; t++) s[row][sub * 16 + t] = vals[t] * inv;
    }
    __syncthreads();

    // O = S @ V ; each warp handles 8 rows, lane = channel d
    {
        const int d = tid & 31;
        const int wslot = tid >> 5;   // 0..7
        float acc[8];
        #pragma unroll
        for (int rr = 0; rr < 8; rr++) acc[rr] = 0.f;

        #pragma unroll 8
        for (int j = 0; j < 64; j++) {
            float vv = v[j][d];
            #pragma unroll
            for (int rr = 0; rr < 8; rr++)
                acc[rr] += s[wslot * 8 + rr][j] * vv;
        }
        #pragma unroll
        for (int rr = 0; rr < 8; rr++) {
            int i = wslot * 8 + rr;
            int gh = wh * 8 + (i >> 3);
            int gw = ww * 8 + (i & 7);
            size_t grow = (size_t)b * (HDIM * WDIM) + (size_t)gh * WDIM + gw;
            att[grow * CDIM + h * HEADD + d] = acc[rr];
        }
    }
}

// ---------------------------------------------------------------------------
extern "C" void kernel_launch(void* const* d_in, const int* in_sizes, int n_in,
                              void* d_out, int out_size)
{
    const float* x      = (const float*)d_in[0];
    const float* qkv_w  = (const float*)d_in[1];
    const float* qkv_b  = (const float*)d_in[2];
    const float* proj_w = (const float*)d_in[3];
    const float* proj_b = (const float*)d_in[4];
    const float* bias   = (const float*)d_in[5];
    float* out = (float*)d_out;

    static float* qkv_ptr = nullptr;
    static float* att_ptr = nullptr;
    if (!qkv_ptr) {
        cudaGetSymbolAddress((void**)&qkv_ptr, g_qkv);
        cudaGetSymbolAddress((void**)&att_ptr, g_att);
    }

    // 1) QKV GEMM: (262144 x 576) = x (262144 x 192) @ qkv_w^T + qkv_b
    sgemm_bias<<<dim3(NQKV / BN, M_TOK / BM), 256>>>(
        x, qkv_w, qkv_b, qkv_ptr, M_TOK, NQKV, CDIM);

    // 2) Windowed attention per (window, head)
    win_attn<<<dim3(NWIN, NHEAD), 256>>>(bias, qkv_ptr, att_ptr);

    // 3) Projection GEMM: out = att @ proj_w^T + proj_b
    sgemm_bias<<<dim3(CDIM / BN, M_TOK / BM), 256>>>(
        att_ptr, proj_w, proj_b, out, M_TOK, CDIM, CDIM);
}

// round 3
// speedup vs baseline: 1.9488x; 1.9488x over previous
#include <cuda_runtime.h>
#include <cstdint>

// Problem constants (fixed by the reference setup)
#define BATCH   4
#define HDIM    256
#define WDIM    256
#define CDIM    192
#define NHEAD   6
#define HEADD   32
#define M_TOK   (BATCH * HDIM * WDIM)   // 262144 tokens
#define NQKV    (3 * CDIM)              // 576
#define NWIN    (BATCH * (HDIM / 8) * (WDIM / 8))  // 4096 windows

// Scratch (no cudaMalloc allowed)
__device__ float g_qkv[(size_t)M_TOK * NQKV];   // 604 MB
__device__ float g_att[(size_t)M_TOK * CDIM];   // 201 MB

// ---------------------------------------------------------------------------
// Helpers
// ---------------------------------------------------------------------------
__device__ __forceinline__ uint32_t smem_u32(const void* p) {
    return (uint32_t)__cvta_generic_to_shared(p);
}

__device__ __forceinline__ void cp_async16(uint32_t dst, const void* src) {
    asm volatile("cp.async.cg.shared.global [%0], [%1], 16;\n" :: "r"(dst), "l"(src));
}

__device__ __forceinline__ uint32_t f2tf32(float f) {
    uint32_t r;
    asm("cvt.rna.tf32.f32 %0, %1;" : "=r"(r) : "f"(f));
    return r;
}

__device__ __forceinline__ void mma_tf32(float* d, const uint32_t* a, const uint32_t* b) {
    asm volatile(
        "mma.sync.aligned.m16n8k8.row.col.f32.tf32.tf32.f32 "
        "{%0,%1,%2,%3}, {%4,%5,%6,%7}, {%8,%9}, {%0,%1,%2,%3};"
        : "+f"(d[0]), "+f"(d[1]), "+f"(d[2]), "+f"(d[3])
        : "r"(a[0]), "r"(a[1]), "r"(a[2]), "r"(a[3]), "r"(b[0]), "r"(b[1]));
}

// ---------------------------------------------------------------------------
// tf32 mma.sync GEMM: C[M,N] = A[M,K] @ W[N,K]^T + bias[N]
// Tile 128x64x16, 256 threads, 8 warps (4M x 2N), each warp 32x32.
// SMEM swizzled at 16B units: phys_unit = row*4 + (q ^ ((row>>1)&3)),
// making both cp.async stores and all mma fragment LDS conflict-free.
// ---------------------------------------------------------------------------
#define BM 128
#define BN 64
#define BK 16

__global__ __launch_bounds__(256) void gemm_tc(
    const float* __restrict__ A, const float* __restrict__ W,
    const float* __restrict__ bias, float* __restrict__ C,
    int M, int N, int K)
{
    __shared__ float sA[2][BM * BK];   // 8 KB per stage
    __shared__ float sB[2][BN * BK];   // 4 KB per stage

    const int tid = threadIdx.x;
    const int wid = tid >> 5;
    const int lane = tid & 31;
    const int g   = lane >> 2;    // groupID (0..7)
    const int tig = lane & 3;     // thread-in-group (0..3)

    const int warp_m = wid & 3;   // 4 warps along M (32 rows each)
    const int warp_n = wid >> 2;  // 2 warps along N (32 cols each)

    const int bm = blockIdx.y * BM;
    const int bn = blockIdx.x * BN;

    float acc[2][4][4];
    #pragma unroll
    for (int mt = 0; mt < 2; mt++)
        #pragma unroll
        for (int nt = 0; nt < 4; nt++)
            #pragma unroll
            for (int r = 0; r < 4; r++) acc[mt][nt][r] = 0.f;

    // Per-thread fragment row indices + swizzle constants
    int mA0[2], mA1[2], cmA0[2], cmA1[2];
    #pragma unroll
    for (int mt = 0; mt < 2; mt++) {
        mA0[mt] = warp_m * 32 + mt * 16 + g;
        mA1[mt] = mA0[mt] + 8;
        cmA0[mt] = (mA0[mt] >> 1) & 3;
        cmA1[mt] = (mA1[mt] >> 1) & 3;
    }
    int nB[4], cnB[4];
    #pragma unroll
    for (int nt = 0; nt < 4; nt++) {
        nB[nt] = warp_n * 32 + nt * 8 + g;
        cnB[nt] = (nB[nt] >> 1) & 3;
    }

    const int nch = K / BK;

    // ---- staging lambda (cp.async, swizzled units) ----
    auto stage = [&](int st, int c) {
        const int k0 = c * BK;
        // A: 512 16B-units, 2 per thread
        #pragma unroll
        for (int i = 0; i < 2; i++) {
            int idx = tid + i * 256;
            int m = idx >> 2, q = idx & 3;
            int pu = m * 4 + (q ^ ((m >> 1) & 3));
            cp_async16(smem_u32(&sA[st][pu * 4]),
                       A + (size_t)(bm + m) * K + k0 + q * 4);
        }
        // B: 256 16B-units, 1 per thread
        {
            int n = tid >> 2, q = tid & 3;
            int pu = n * 4 + (q ^ ((n >> 1) & 3));
            cp_async16(smem_u32(&sB[st][pu * 4]),
                       W + (size_t)(bn + n) * K + k0 + q * 4);
        }
        asm volatile("cp.async.commit_group;" ::: "memory");
    };

    stage(0, 0);

    for (int c = 0; c < nch; c++) {
        const int st = c & 1;
        if (c + 1 < nch) {
            stage(st ^ 1, c + 1);
            asm volatile("cp.async.wait_group 1;" ::: "memory");
        } else {
            asm volatile("cp.async.wait_group 0;" ::: "memory");
        }
        __syncthreads();

        #pragma unroll
        for (int s = 0; s < 2; s++) {
            const int q0 = 2 * s, q1 = 2 * s + 1;

            uint32_t afr[2][4];
            #pragma unroll
            for (int mt = 0; mt < 2; mt++) {
                afr[mt][0] = f2tf32(sA[st][mA0[mt] * 16 + (q0 ^ cmA0[mt]) * 4 + tig]);
                afr[mt][1] = f2tf32(sA[st][mA1[mt] * 16 + (q0 ^ cmA1[mt]) * 4 + tig]);
                afr[mt][2] = f2tf32(sA[st][mA0[mt] * 16 + (q1 ^ cmA0[mt]) * 4 + tig]);
                afr[mt][3] = f2tf32(sA[st][mA1[mt] * 16 + (q1 ^ cmA1[mt]) * 4 + tig]);
            }
            uint32_t bfr[4][2];
            #pragma unroll
            for (int nt = 0; nt < 4; nt++) {
                bfr[nt][0] = f2tf32(sB[st][nB[nt] * 16 + (q0 ^ cnB[nt]) * 4 + tig]);
                bfr[nt][1] = f2tf32(sB[st][nB[nt] * 16 + (q1 ^ cnB[nt]) * 4 + tig]);
            }
            #pragma unroll
            for (int mt = 0; mt < 2; mt++)
                #pragma unroll
                for (int nt = 0; nt < 4; nt++)
                    mma_tf32(acc[mt][nt], afr[mt], bfr[nt]);
        }
        __syncthreads();
    }

    // ---- epilogue: bias + store ----
    #pragma unroll
    for (int nt = 0; nt < 4; nt++) {
        int n = bn + warp_n * 32 + nt * 8 + tig * 2;
        float2 bv = *(const float2*)&bias[n];
        #pragma unroll
        for (int mt = 0; mt < 2; mt++) {
            int m = bm + warp_m * 32 + mt * 16 + g;
            float2 v0 = make_float2(acc[mt][nt][0] + bv.x, acc[mt][nt][1] + bv.y);
            float2 v1 = make_float2(acc[mt][nt][2] + bv.x, acc[mt][nt][3] + bv.y);
            *(float2*)(C + (size_t)m * N + n)       = v0;
            *(float2*)(C + (size_t)(m + 8) * N + n) = v1;
        }
    }
}

// ---------------------------------------------------------------------------
// Window attention: one block per (window, head). 256 threads. (unchanged)
// ---------------------------------------------------------------------------
__global__ __launch_bounds__(256) void win_attn(
    const float* __restrict__ bias,
    const float* __restrict__ qkv,
    float* __restrict__ att)
{
    __shared__ float q[64][33];
    __shared__ float k[64][33];
    __shared__ float v[64][33];
    __shared__ float s[64][65];

    const int win = blockIdx.x;
    const int h   = blockIdx.y;
    const int tid = threadIdx.x;

    const int b  = win >> 10;
    const int r  = win & 1023;
    const int wh = r >> 5;
    const int ww = r & 31;

    const float scale = 0.17677669529663687f;  // 1/sqrt(32)

    for (int idx = tid; idx < 64 * 32; idx += 256) {
        int i = idx >> 5, d = idx & 31;
        int gh = wh * 8 + (i >> 3);
        int gw = ww * 8 + (i & 7);
        size_t grow = (size_t)b * (HDIM * WDIM) + (size_t)gh * WDIM + gw;
        const float* base = qkv + grow * NQKV + h * HEADD + d;
        q[i][d] = base[0] * scale;
        k[i][d] = base[CDIM];
        v[i][d] = base[2 * CDIM];
    }
    __syncthreads();

    {
        const int tx = tid & 15, ty = tid >> 4;
        float acc[4][4];
        #pragma unroll
        for (int ii = 0; ii < 4; ii++)
            #pragma unroll
            for (int jj = 0; jj < 4; jj++) acc[ii][jj] = 0.f;

        #pragma unroll
        for (int d = 0; d < 32; d++) {
            float a[4], bb[4];
            #pragma unroll
            for (int ii = 0; ii < 4; ii++) a[ii] = q[ty * 4 + ii][d];
            #pragma unroll
            for (int jj = 0; jj < 4; jj++) bb[jj] = k[tx * 4 + jj][d];
            #pragma unroll
            for (int ii = 0; ii < 4; ii++)
                #pragma unroll
                for (int jj = 0; jj < 4; jj++) acc[ii][jj] += a[ii] * bb[jj];
        }
        #pragma unroll
        for (int ii = 0; ii < 4; ii++) {
            int i = ty * 4 + ii;
            #pragma unroll
            for (int jj = 0; jj < 4; jj++) {
                int j = tx * 4 + jj;
                s[i][j] = acc[ii][jj] + bias[((size_t)h * 64 + i) * 64 + j];
            }
        }
    }
    __syncthreads();

    {
        const int row = tid >> 2, sub = tid & 3;
        float vals[16];
        float mx = -1e30f;
        #pragma unroll
        for (int t = 0; t < 16; t++) {
            vals[t] = s[row][sub * 16 + t];
            mx = fmaxf(mx, vals[t]);
        }
        mx = fmaxf(mx, __shfl_xor_sync(0xffffffffu, mx, 1));
        mx = fmaxf(mx, __shfl_xor_sync(0xffffffffu, mx, 2));
        float sum = 0.f;
        #pragma unroll
        for (int t = 0; t < 16; t++) {
            vals[t] = __expf(vals[t] - mx);
            sum += vals[t];
        }
        sum += __shfl_xor_sync(0xffffffffu, sum, 1);
        sum += __shfl_xor_sync(0xffffffffu, sum, 2);
        float inv = __frcp_rn(sum);
        #pragma unroll
        for (int t = 0; t < 16; t++) s[row][sub * 16 + t] = vals[t] * inv;
    }
    __syncthreads();

    {
        const int d = tid & 31;
        const int wslot = tid >> 5;
        float acc[8];
        #pragma unroll
        for (int rr = 0; rr < 8; rr++) acc[rr] = 0.f;

        #pragma unroll 8
        for (int j = 0; j < 64; j++) {
            float vv = v[j][d];
            #pragma unroll
            for (int rr = 0; rr < 8; rr++)
                acc[rr] += s[wslot * 8 + rr][j] * vv;
        }
        #pragma unroll
        for (int rr = 0; rr < 8; rr++) {
            int i = wslot * 8 + rr;
            int gh = wh * 8 + (i >> 3);
            int gw = ww * 8 + (i & 7);
            size_t grow = (size_t)b * (HDIM * WDIM) + (size_t)gh * WDIM + gw;
            att[grow * CDIM + h * HEADD + d] = acc[rr];
        }
    }
}

// ---------------------------------------------------------------------------
extern "C" void kernel_launch(void* const* d_in, const int* in_sizes, int n_in,
                              void* d_out, int out_size)
{
    const float* x      = (const float*)d_in[0];
    const float* qkv_w  = (const float*)d_in[1];
    const float* qkv_b  = (const float*)d_in[2];
    const float* proj_w = (const float*)d_in[3];
    const float* proj_b = (const float*)d_in[4];
    const float* bias   = (const float*)d_in[5];
    float* out = (float*)d_out;

    static float* qkv_ptr = nullptr;
    static float* att_ptr = nullptr;
    if (!qkv_ptr) {
        cudaGetSymbolAddress((void**)&qkv_ptr, g_qkv);
        cudaGetSymbolAddress((void**)&att_ptr, g_att);
    }

    // 1) QKV GEMM: (262144 x 576) = x @ qkv_w^T + qkv_b   (tf32 mma.sync)
    gemm_tc<<<dim3(NQKV / BN, M_TOK / BM), 256>>>(
        x, qkv_w, qkv_b, qkv_ptr, M_TOK, NQKV, CDIM);

    // 2) Windowed attention per (window, head)
    win_attn<<<dim3(NWIN, NHEAD), 256>>>(bias, qkv_ptr, att_ptr);

    // 3) Projection GEMM: out = att @ proj_w^T + proj_b   (tf32 mma.sync)
    gemm_tc<<<dim3(CDIM / BN, M_TOK / BM), 256>>>(
        att_ptr, proj_w, proj_b, out, M_TOK, CDIM, CDIM);
}

// round 6
// speedup vs baseline: 2.6787x; 1.3746x over previous
#include <cuda_runtime.h>
#include <cstdint>

// Problem constants (fixed by the reference setup)
#define BATCH   4
#define HDIM    256
#define WDIM    256
#define CDIM    192
#define NHEAD   6
#define HEADD   32
#define M_TOK   (BATCH * HDIM * WDIM)   // 262144 tokens
#define NQKV    (3 * CDIM)              // 576
#define NWIN    (BATCH * (HDIM / 8) * (WDIM / 8))  // 4096 windows

// Scratch (no cudaMalloc allowed)
__device__ float g_qkv[(size_t)M_TOK * NQKV];   // 604 MB
__device__ float g_att[(size_t)M_TOK * CDIM];   // 201 MB

// ---------------------------------------------------------------------------
// Helpers
// ---------------------------------------------------------------------------
__device__ __forceinline__ uint32_t smem_u32(const void* p) {
    return (uint32_t)__cvta_generic_to_shared(p);
}

__device__ __forceinline__ void cp_async16(uint32_t dst, const void* src) {
    asm volatile("cp.async.cg.shared.global [%0], [%1], 16;\n" :: "r"(dst), "l"(src));
}

// Round-to-nearest tf32 conversion. Truncation (raw bits) measured +0.8e-3
// rel_err across the 4-stage pipeline — must keep the rounding.
__device__ __forceinline__ uint32_t f2tf32(float f) {
    uint32_t r;
    asm("cvt.rna.tf32.f32 %0, %1;" : "=r"(r) : "f"(f));
    return r;
}

__device__ __forceinline__ void mma_tf32(float* d, const uint32_t* a, const uint32_t* b) {
    asm volatile(
        "mma.sync.aligned.m16n8k8.row.col.f32.tf32.tf32.f32 "
        "{%0,%1,%2,%3}, {%4,%5,%6,%7}, {%8,%9}, {%0,%1,%2,%3};"
        : "+f"(d[0]), "+f"(d[1]), "+f"(d[2]), "+f"(d[3])
        : "r"(a[0]), "r"(a[1]), "r"(a[2]), "r"(a[3]), "r"(b[0]), "r"(b[1]));
}

// ---------------------------------------------------------------------------
// tf32 mma.sync GEMM: C[M,N] = A[M,K] @ W[N,K]^T + bias[N]
// Tile 128x64x16, 256 threads, 8 warps (4M x 2N), each warp 32x32.
// ---------------------------------------------------------------------------
#define BM 128
#define BN 64
#define BK 16

__global__ __launch_bounds__(256) void gemm_tc(
    const float* __restrict__ A, const float* __restrict__ W,
    const float* __restrict__ bias, float* __restrict__ C,
    int M, int N, int K)
{
    __shared__ float sA[2][BM * BK];   // 8 KB per stage
    __shared__ float sB[2][BN * BK];   // 4 KB per stage

    const int tid = threadIdx.x;
    const int wid = tid >> 5;
    const int lane = tid & 31;
    const int g   = lane >> 2;
    const int tig = lane & 3;

    const int warp_m = wid & 3;
    const int warp_n = wid >> 2;

    const int bm = blockIdx.y * BM;
    const int bn = blockIdx.x * BN;

    float acc[2][4][4];
    #pragma unroll
    for (int mt = 0; mt < 2; mt++)
        #pragma unroll
        for (int nt = 0; nt < 4; nt++)
            #pragma unroll
            for (int r = 0; r < 4; r++) acc[mt][nt][r] = 0.f;

    int mA0[2], mA1[2], cmA0[2], cmA1[2];
    #pragma unroll
    for (int mt = 0; mt < 2; mt++) {
        mA0[mt] = warp_m * 32 + mt * 16 + g;
        mA1[mt] = mA0[mt] + 8;
        cmA0[mt] = (mA0[mt] >> 1) & 3;
        cmA1[mt] = (mA1[mt] >> 1) & 3;
    }
    int nB[4], cnB[4];
    #pragma unroll
    for (int nt = 0; nt < 4; nt++) {
        nB[nt] = warp_n * 32 + nt * 8 + g;
        cnB[nt] = (nB[nt] >> 1) & 3;
    }

    const int nch = K / BK;

    auto stage = [&](int st, int c) {
        const int k0 = c * BK;
        #pragma unroll
        for (int i = 0; i < 2; i++) {
            int idx = tid + i * 256;
            int m = idx >> 2, q = idx & 3;
            int pu = m * 4 + (q ^ ((m >> 1) & 3));
            cp_async16(smem_u32(&sA[st][pu * 4]),
                       A + (size_t)(bm + m) * K + k0 + q * 4);
        }
        {
            int n = tid >> 2, q = tid & 3;
            int pu = n * 4 + (q ^ ((n >> 1) & 3));
            cp_async16(smem_u32(&sB[st][pu * 4]),
                       W + (size_t)(bn + n) * K + k0 + q * 4);
        }
        asm volatile("cp.async.commit_group;" ::: "memory");
    };

    stage(0, 0);

    for (int c = 0; c < nch; c++) {
        const int st = c & 1;
        if (c + 1 < nch) {
            stage(st ^ 1, c + 1);
            asm volatile("cp.async.wait_group 1;" ::: "memory");
        } else {
            asm volatile("cp.async.wait_group 0;" ::: "memory");
        }
        __syncthreads();

        #pragma unroll
        for (int s = 0; s < 2; s++) {
            const int q0 = 2 * s, q1 = 2 * s + 1;

            uint32_t afr[2][4];
            #pragma unroll
            for (int mt = 0; mt < 2; mt++) {
                afr[mt][0] = f2tf32(sA[st][mA0[mt] * 16 + (q0 ^ cmA0[mt]) * 4 + tig]);
                afr[mt][1] = f2tf32(sA[st][mA1[mt] * 16 + (q0 ^ cmA1[mt]) * 4 + tig]);
                afr[mt][2] = f2tf32(sA[st][mA0[mt] * 16 + (q1 ^ cmA0[mt]) * 4 + tig]);
                afr[mt][3] = f2tf32(sA[st][mA1[mt] * 16 + (q1 ^ cmA1[mt]) * 4 + tig]);
            }
            uint32_t bfr[4][2];
            #pragma unroll
            for (int nt = 0; nt < 4; nt++) {
                bfr[nt][0] = f2tf32(sB[st][nB[nt] * 16 + (q0 ^ cnB[nt]) * 4 + tig]);
                bfr[nt][1] = f2tf32(sB[st][nB[nt] * 16 + (q1 ^ cnB[nt]) * 4 + tig]);
            }
            #pragma unroll
            for (int mt = 0; mt < 2; mt++)
                #pragma unroll
                for (int nt = 0; nt < 4; nt++)
                    mma_tf32(acc[mt][nt], afr[mt], bfr[nt]);
        }
        __syncthreads();
    }

    #pragma unroll
    for (int nt = 0; nt < 4; nt++) {
        int n = bn + warp_n * 32 + nt * 8 + tig * 2;
        float2 bv = *(const float2*)&bias[n];
        #pragma unroll
        for (int mt = 0; mt < 2; mt++) {
            int m = bm + warp_m * 32 + mt * 16 + g;
            float2 v0 = make_float2(acc[mt][nt][0] + bv.x, acc[mt][nt][1] + bv.y);
            float2 v1 = make_float2(acc[mt][nt][2] + bv.x, acc[mt][nt][3] + bv.y);
            *(float2*)(C + (size_t)m * N + n)       = v0;
            *(float2*)(C + (size_t)(m + 8) * N + n) = v1;
        }
    }
}

// ---------------------------------------------------------------------------
// Tensor-core window attention.
// One block per window; 384 threads = 12 warps = (6 heads) x (2 M-halves).
// SMEM per head (floats): q[64][36] @0, k[64][36] @2304, vT[32][68] @4608
//   (head stride 6784). After S, P[64][68] overlays q+k (pair bar.sync).
// All MMA fragment LDS patterns are bank-conflict-free (bank = 4g+tig).
// ---------------------------------------------------------------------------
#define HSTR 6784
#define WT_SMEM (6 * HSTR * 4)

extern __shared__ float ws[];

__global__ __launch_bounds__(384) void win_attn_tc(
    const float* __restrict__ bias,
    const float* __restrict__ qkv,
    float* __restrict__ att)
{
    const int tid  = threadIdx.x;
    const int wid  = tid >> 5;
    const int lane = tid & 31;
    const int g    = lane >> 2;
    const int tig  = lane & 3;
    const int hl   = wid >> 1;     // head 0..5
    const int mh   = wid & 1;      // M-half

    const int win = blockIdx.x;
    const int b   = win >> 10;
    const int r_  = win & 1023;
    const int wh  = r_ >> 5;
    const int ww  = r_ & 31;

    const float scale = 0.17677669529663687f;  // 1/sqrt(32)

    // ---- load q (scaled), k, vT for all 6 heads ----
    for (int idx4 = tid; idx4 < 3072; idx4 += 384) {
        int i  = idx4 / 48;        // token in window
        int c  = idx4 % 48;
        int lh = c >> 3;           // head
        int d  = (c & 7) * 4;      // dim
        int gh = wh * 8 + (i >> 3);
        int gw = ww * 8 + (i & 7);
        size_t tok = (size_t)b * (HDIM * WDIM) + (size_t)gh * WDIM + gw;
        const float* base = qkv + tok * NQKV + lh * HEADD + d;
        float4 qv = *(const float4*)base;
        float4 kv = *(const float4*)(base + CDIM);
        float4 vv = *(const float4*)(base + 2 * CDIM);
        float* hp = ws + lh * HSTR;
        qv.x *= scale; qv.y *= scale; qv.z *= scale; qv.w *= scale;
        *(float4*)&hp[i * 36 + d] = qv;
        *(float4*)&hp[2304 + i * 36 + d] = kv;
        hp[4608 + (d + 0) * 68 + i] = vv.x;
        hp[4608 + (d + 1) * 68 + i] = vv.y;
        hp[4608 + (d + 2) * 68 + i] = vv.z;
        hp[4608 + (d + 3) * 68 + i] = vv.w;
    }
    __syncthreads();

    float* hb = ws + hl * HSTR;
    const float* q_s = hb;          // [64][36]
    const float* k_s = hb + 2304;   // [64][36]
    const float* vT  = hb + 4608;   // [32][68]
    const int rbase = mh * 32;

    // ---- S = q @ k^T (32x64x32 per warp) ----
    float accS[2][8][4];
    #pragma unroll
    for (int mt = 0; mt < 2; mt++)
        #pragma unroll
        for (int nt = 0; nt < 8; nt++)
            #pragma unroll
            for (int r = 0; r < 4; r++) accS[mt][nt][r] = 0.f;

    #pragma unroll
    for (int ks = 0; ks < 4; ks++) {
        const int k0 = ks * 8;
        uint32_t afr[2][4];
        #pragma unroll
        for (int mt = 0; mt < 2; mt++) {
            int r0 = rbase + mt * 16 + g;
            afr[mt][0] = f2tf32(q_s[r0 * 36 + k0 + tig]);
            afr[mt][1] = f2tf32(q_s[(r0 + 8) * 36 + k0 + tig]);
            afr[mt][2] = f2tf32(q_s[r0 * 36 + k0 + 4 + tig]);
            afr[mt][3] = f2tf32(q_s[(r0 + 8) * 36 + k0 + 4 + tig]);
        }
        uint32_t bfr[8][2];
        #pragma unroll
        for (int nt = 0; nt < 8; nt++) {
            int n = nt * 8 + g;
            bfr[nt][0] = f2tf32(k_s[n * 36 + k0 + tig]);
            bfr[nt][1] = f2tf32(k_s[n * 36 + k0 + 4 + tig]);
        }
        #pragma unroll
        for (int mt = 0; mt < 2; mt++)
            #pragma unroll
            for (int nt = 0; nt < 8; nt++)
                mma_tf32(accS[mt][nt], afr[mt], bfr[nt]);
    }

    // ---- + bias ----
    {
        const float* bp = bias + (size_t)hl * 64 * 64;
        #pragma unroll
        for (int mt = 0; mt < 2; mt++) {
            int r0 = rbase + mt * 16 + g;
            #pragma unroll
            for (int nt = 0; nt < 8; nt++) {
                int c0 = nt * 8 + tig * 2;
                float2 b0 = *(const float2*)(bp + r0 * 64 + c0);
                float2 b1 = *(const float2*)(bp + (r0 + 8) * 64 + c0);
                accS[mt][nt][0] += b0.x;
                accS[mt][nt][1] += b0.y;
                accS[mt][nt][2] += b1.x;
                accS[mt][nt][3] += b1.y;
            }
        }
    }

    // ---- softmax (rows live in a lane quad) ----
    #pragma unroll
    for (int mt = 0; mt < 2; mt++) {
        float mx0 = -1e30f, mx1 = -1e30f;
        #pragma unroll
        for (int nt = 0; nt < 8; nt++) {
            mx0 = fmaxf(mx0, fmaxf(accS[mt][nt][0], accS[mt][nt][1]));
            mx1 = fmaxf(mx1, fmaxf(accS[mt][nt][2], accS[mt][nt][3]));
        }
        mx0 = fmaxf(mx0, __shfl_xor_sync(0xffffffffu, mx0, 1));
        mx0 = fmaxf(mx0, __shfl_xor_sync(0xffffffffu, mx0, 2));
        mx1 = fmaxf(mx1, __shfl_xor_sync(0xffffffffu, mx1, 1));
        mx1 = fmaxf(mx1, __shfl_xor_sync(0xffffffffu, mx1, 2));
        float s0 = 0.f, s1 = 0.f;
        #pragma unroll
        for (int nt = 0; nt < 8; nt++) {
            accS[mt][nt][0] = __expf(accS[mt][nt][0] - mx0);
            accS[mt][nt][1] = __expf(accS[mt][nt][1] - mx0);
            accS[mt][nt][2] = __expf(accS[mt][nt][2] - mx1);
            accS[mt][nt][3] = __expf(accS[mt][nt][3] - mx1);
            s0 += accS[mt][nt][0] + accS[mt][nt][1];
            s1 += accS[mt][nt][2] + accS[mt][nt][3];
        }
        s0 += __shfl_xor_sync(0xffffffffu, s0, 1);
        s0 += __shfl_xor_sync(0xffffffffu, s0, 2);
        s1 += __shfl_xor_sync(0xffffffffu, s1, 1);
        s1 += __shfl_xor_sync(0xffffffffu, s1, 2);
        float i0 = __frcp_rn(s0), i1 = __frcp_rn(s1);
        #pragma unroll
        for (int nt = 0; nt < 8; nt++) {
            accS[mt][nt][0] *= i0;
            accS[mt][nt][1] *= i0;
            accS[mt][nt][2] *= i1;
            accS[mt][nt][3] *= i1;
        }
    }

    // ---- pair barrier, then P overlays q+k of this head ----
    asm volatile("bar.sync %0, %1;" :: "r"(1 + hl), "r"(64) : "memory");

    float* p_s = hb;   // [64][68]
    #pragma unroll
    for (int mt = 0; mt < 2; mt++) {
        int r0 = rbase + mt * 16 + g;
        #pragma unroll
        for (int nt = 0; nt < 8; nt++) {
            int c0 = nt * 8 + tig * 2;
            *(float2*)&p_s[r0 * 68 + c0] =
                make_float2(accS[mt][nt][0], accS[mt][nt][1]);
            *(float2*)&p_s[(r0 + 8) * 68 + c0] =
                make_float2(accS[mt][nt][2], accS[mt][nt][3]);
        }
    }

    // ---- O = P @ V (32x32x64 per warp) ----
    float accO[2][4][4];
    #pragma unroll
    for (int mt = 0; mt < 2; mt++)
        #pragma unroll
        for (int nt = 0; nt < 4; nt++)
            #pragma unroll
            for (int r = 0; r < 4; r++) accO[mt][nt][r] = 0.f;

    // pair barrier: P stores must be visible to both warps of this head
    asm volatile("bar.sync %0, %1;" :: "r"(1 + hl), "r"(64) : "memory");

    #pragma unroll
    for (int ks = 0; ks < 8; ks++) {
        const int k0 = ks * 8;
        uint32_t afr[2][4];
        #pragma unroll
        for (int mt = 0; mt < 2; mt++) {
            int r0 = rbase + mt * 16 + g;
            afr[mt][0] = f2tf32(p_s[r0 * 68 + k0 + tig]);
            afr[mt][1] = f2tf32(p_s[(r0 + 8) * 68 + k0 + tig]);
            afr[mt][2] = f2tf32(p_s[r0 * 68 + k0 + 4 + tig]);
            afr[mt][3] = f2tf32(p_s[(r0 + 8) * 68 + k0 + 4 + tig]);
        }
        uint32_t bfr[4][2];
        #pragma unroll
        for (int nt = 0; nt < 4; nt++) {
            int n = nt * 8 + g;
            bfr[nt][0] = f2tf32(vT[n * 68 + k0 + tig]);
            bfr[nt][1] = f2tf32(vT[n * 68 + k0 + 4 + tig]);
        }
        #pragma unroll
        for (int mt = 0; mt < 2; mt++)
            #pragma unroll
            for (int nt = 0; nt < 4; nt++)
                mma_tf32(accO[mt][nt], afr[mt], bfr[nt]);
    }

    // ---- store O ----
    #pragma unroll
    for (int mt = 0; mt < 2; mt++) {
        int r0 = rbase + mt * 16 + g;
        #pragma unroll
        for (int half = 0; half < 2; half++) {
            int i = r0 + half * 8;
            int gh = wh * 8 + (i >> 3);
            int gw = ww * 8 + (i & 7);
            size_t tok = (size_t)b * (HDIM * WDIM) + (size_t)gh * WDIM + gw;
            float* orow = att + tok * CDIM + hl * HEADD;
            #pragma unroll
            for (int nt = 0; nt < 4; nt++) {
                int c0 = nt * 8 + tig * 2;
                *(float2*)(orow + c0) =
                    make_float2(accO[mt][nt][half * 2], accO[mt][nt][half * 2 + 1]);
            }
        }
    }
}

// ---------------------------------------------------------------------------
extern "C" void kernel_launch(void* const* d_in, const int* in_sizes, int n_in,
                              void* d_out, int out_size)
{
    const float* x      = (const float*)d_in[0];
    const float* qkv_w  = (const float*)d_in[1];
    const float* qkv_b  = (const float*)d_in[2];
    const float* proj_w = (const float*)d_in[3];
    const float* proj_b = (const float*)d_in[4];
    const float* bias   = (const float*)d_in[5];
    float* out = (float*)d_out;

    static float* qkv_ptr = nullptr;
    static float* att_ptr = nullptr;
    if (!qkv_ptr) {
        cudaGetSymbolAddress((void**)&qkv_ptr, g_qkv);
        cudaGetSymbolAddress((void**)&att_ptr, g_att);
    }
    cudaFuncSetAttribute(win_attn_tc,
                         cudaFuncAttributeMaxDynamicSharedMemorySize, WT_SMEM);

    // 1) QKV GEMM: (262144 x 576) = x @ qkv_w^T + qkv_b   (tf32 mma.sync)
    gemm_tc<<<dim3(NQKV / BN, M_TOK / BM), 256>>>(
        x, qkv_w, qkv_b, qkv_ptr, M_TOK, NQKV, CDIM);

    // 2) Windowed attention (tensor cores), one block per window
    win_attn_tc<<<NWIN, 384, WT_SMEM>>>(bias, qkv_ptr, att_ptr);

    // 3) Projection GEMM: out = att @ proj_w^T + proj_b   (tf32 mma.sync)
    gemm_tc<<<dim3(CDIM / BN, M_TOK / BM), 256>>>(
        att_ptr, proj_w, proj_b, out, M_TOK, CDIM, CDIM);
}